// round 11
// baseline (speedup 1.0000x reference)
#include <cuda_runtime.h>
#include <cuda_fp16.h>
#include <math.h>
#include <stdint.h>

#define N_NODES 50000
#define N_EDGES 1600000
#define E_TOT   1650000   // + self loops
#define NEG_SLOPE 0.2f

#define SBLK 256
#define NBLOCKS_SCAN ((N_NODES + SBLK - 1) / SBLK)   // 196
#define STAGE 128        // per-warp smem staging capacity (deg is Poisson(33))
#define XPITCH 132       // padded smem row pitch (16B-aligned, bank-shifted)

// ---------------- scratch (device globals; only referenced from device code) ----------------
__device__ __align__(16) __half2 g_xl1h[N_NODES * 64];  // layer1 feats, fp16 [N,128]
__device__ __align__(16) __half2 g_xl2h[N_NODES * 32];  // layer2 feats, fp16 [N,64]
__device__ __align__(16) float   g_as1[N_NODES * 2];
__device__ __align__(16) float   g_ad1[N_NODES * 2];
__device__ __align__(16) float   g_as2[N_NODES];
__device__ __align__(16) float   g_ad2[N_NODES];

__device__ __align__(16) int   g_deg [N_NODES];
__device__ __align__(16) int   g_ptr [N_NODES + 1];
__device__ __align__(16) int   g_work[N_NODES];
__device__ __align__(16) int   g_src_csr[E_TOT];
__device__ __align__(16) float g_e_csr[E_TOT * 2];   // fallback only (deg > STAGE)
__device__ __align__(16) int   g_bsum[NBLOCKS_SCAN];

__device__ int g_e64;

// ---------------- helpers ----------------
__device__ __forceinline__ float lrelu(float x) {
    return x >= 0.0f ? x : NEG_SLOPE * x;
}

__device__ __forceinline__ void edge_sd(const void* ei, int is64, int e, int& s, int& d) {
    if (e >= N_EDGES) { s = d = e - N_EDGES; return; }
    if (is64) {
        const long long* p = (const long long*)ei;
        s = (int)p[e];
        d = (int)p[N_EDGES + e];
    } else {
        const int* p = (const int*)ei;
        s = p[e];
        d = p[N_EDGES + e];
    }
}

__device__ __forceinline__ int warp_incl_scan(int v, int lane) {
#pragma unroll
    for (int off = 1; off < 32; off <<= 1) {
        int n = __shfl_up_sync(0xffffffff, v, off);
        if (lane >= off) v += n;
    }
    return v;
}

// ---------------- graph preprocessing ----------------
__global__ void prep_kernel(const long long* ei) {
    int i = blockIdx.x * blockDim.x + threadIdx.x;
    if (i < N_NODES) g_deg[i] = 0;
    if (blockIdx.x == 0) {
        __shared__ int bad;
        if (threadIdx.x == 0) bad = 0;
        __syncthreads();
        long long v = ei[threadIdx.x];
        if (v < 0 || v >= N_NODES) bad = 1;
        __syncthreads();
        if (threadIdx.x == 0) g_e64 = bad ? 0 : 1;
    }
}

__global__ void hist_kernel(const void* __restrict__ ei) {
    int e = blockIdx.x * blockDim.x + threadIdx.x;
    if (e >= E_TOT) return;
    int s, d; edge_sd(ei, g_e64, e, s, d);
    atomicAdd(&g_deg[d], 1);
}

__global__ void scan_partial_kernel() {
    int i = blockIdx.x * SBLK + threadIdx.x;
    int v = (i < N_NODES) ? g_deg[i] : 0;
    __shared__ int ws[8];
    int lane = threadIdx.x & 31, wid = threadIdx.x >> 5;
    int s = v;
#pragma unroll
    for (int off = 16; off; off >>= 1) s += __shfl_xor_sync(0xffffffff, s, off);
    if (lane == 0) ws[wid] = s;
    __syncthreads();
    if (threadIdx.x == 0) {
        int t = 0;
#pragma unroll
        for (int w = 0; w < 8; w++) t += ws[w];
        g_bsum[blockIdx.x] = t;
    }
}

__global__ void scan_final_kernel() {
    __shared__ int s_boff[NBLOCKS_SCAN];
    __shared__ int ws2[8];
    __shared__ int ws[8];
    int t = threadIdx.x;
    int lane = t & 31, wid = t >> 5;

    {
        int v = (t < NBLOCKS_SCAN) ? g_bsum[t] : 0;
        int inc = warp_incl_scan(v, lane);
        if (lane == 31) ws2[wid] = inc;
        __syncthreads();
        if (wid == 0) {
            int wv = (lane < 8) ? ws2[lane] : 0;
            int winc = warp_incl_scan(wv, lane);
            if (lane < 8) ws2[lane] = winc;
        }
        __syncthreads();
        int excl = inc - v + (wid ? ws2[wid - 1] : 0);
        if (t < NBLOCKS_SCAN) s_boff[t] = excl;
        if (blockIdx.x == 0 && t == NBLOCKS_SCAN - 1) g_ptr[N_NODES] = excl + v;
    }
    __syncthreads();

    int i = blockIdx.x * SBLK + t;
    int v = (i < N_NODES) ? g_deg[i] : 0;
    int inc = warp_incl_scan(v, lane);
    if (lane == 31) ws[wid] = inc;
    __syncthreads();
    if (wid == 0) {
        int wv = (lane < 8) ? ws[lane] : 0;
        int winc = warp_incl_scan(wv, lane);
        if (lane < 8) ws[lane] = winc;
    }
    __syncthreads();
    int excl = inc - v + (wid ? ws[wid - 1] : 0) + s_boff[blockIdx.x];
    if (i < N_NODES) { g_ptr[i] = excl; g_work[i] = excl; }
}

__global__ void scatter_kernel(const void* __restrict__ ei) {
    int e = blockIdx.x * blockDim.x + threadIdx.x;
    if (e >= E_TOT) return;
    int s, d; edge_sd(ei, g_e64, e, s, d);
    int pos = atomicAdd(&g_work[d], 1);
    g_src_csr[pos] = s;
}

// ---------------- layer-1 GEMM (k4-chunked), fp16 output + fused attention logits ----------------
// Tile 64 rows x 128 cols per 256-thread block; thread = 8 rows x 4 cols.
__global__ void gemm1_kernel(const float* __restrict__ X,
                             const float* __restrict__ W,
                             const float* __restrict__ att_src,
                             const float* __restrict__ att_dst) {
    extern __shared__ float sm[];
    float* sX = sm;                       // [64][XPITCH]
    float* sW = sm + 64 * XPITCH;         // [128][128]

    const int tid  = threadIdx.x;
    const int row0 = blockIdx.x * 64;
    const int tc   = tid & 31;            // lane
    const int tr   = tid >> 5;            // warp = thread-row group

    {
        const float4* Wv  = (const float4*)W;
        float4*       sWv = (float4*)sW;
        for (int i = tid; i < 128 * 128 / 4; i += 256) sWv[i] = Wv[i];
    }
    for (int i = tid; i < 64 * 32; i += 256) {
        int r = i >> 5, c4 = i & 31;
        int row = row0 + r;
        float4 v = (row < N_NODES) ? ((const float4*)(X + (size_t)row * 128))[c4]
                                   : make_float4(0.f, 0.f, 0.f, 0.f);
        *(float4*)(sX + r * XPITCH + c4 * 4) = v;
    }
    __syncthreads();

    float acc[8][4];
#pragma unroll
    for (int i = 0; i < 8; i++)
#pragma unroll
        for (int c = 0; c < 4; c++) acc[i][c] = 0.0f;

    const float* xbase = sX + tr * 8 * XPITCH;
#pragma unroll 4
    for (int k4 = 0; k4 < 32; k4++) {
        float4 w0 = *(const float4*)(sW + (k4 * 4 + 0) * 128 + tc * 4);
        float4 w1 = *(const float4*)(sW + (k4 * 4 + 1) * 128 + tc * 4);
        float4 w2 = *(const float4*)(sW + (k4 * 4 + 2) * 128 + tc * 4);
        float4 w3 = *(const float4*)(sW + (k4 * 4 + 3) * 128 + tc * 4);
#pragma unroll
        for (int i = 0; i < 8; i++) {
            float4 a = *(const float4*)(xbase + i * XPITCH + k4 * 4);   // broadcast
            acc[i][0] += a.x * w0.x + a.y * w1.x + a.z * w2.x + a.w * w3.x;
            acc[i][1] += a.x * w0.y + a.y * w1.y + a.z * w2.y + a.w * w3.y;
            acc[i][2] += a.x * w0.z + a.y * w1.z + a.z * w2.z + a.w * w3.z;
            acc[i][3] += a.x * w0.w + a.y * w1.w + a.z * w2.w + a.w * w3.w;
        }
    }

    float4 as4 = ((const float4*)att_src)[tc];
    float4 ad4 = ((const float4*)att_dst)[tc];
#pragma unroll
    for (int i = 0; i < 8; i++) {
        int row = row0 + tr * 8 + i;
        float ps = acc[i][0] * as4.x + acc[i][1] * as4.y + acc[i][2] * as4.z + acc[i][3] * as4.w;
        float pd = acc[i][0] * ad4.x + acc[i][1] * ad4.y + acc[i][2] * ad4.z + acc[i][3] * ad4.w;
#pragma unroll
        for (int off = 8; off; off >>= 1) {
            ps += __shfl_xor_sync(0xffffffffu, ps, off);
            pd += __shfl_xor_sync(0xffffffffu, pd, off);
        }
        if ((tid & 15) == 0 && row < N_NODES) {
            int h = (tid >> 4) & 1;   // lanes 0-15 = cols 0-63 = head 0; 16-31 = head 1
            g_as1[row * 2 + h] = ps;
            g_ad1[row * 2 + h] = pd;
        }
        if (row < N_NODES) {
            __half2 h0 = __floats2half2_rn(acc[i][0], acc[i][1]);
            __half2 h1 = __floats2half2_rn(acc[i][2], acc[i][3]);
            uint2 pk = make_uint2(*(unsigned*)&h0, *(unsigned*)&h1);
            *(uint2*)(g_xl1h + (size_t)row * 64 + tc * 2) = pk;
        }
    }
}

// ---------------- MEGA: layer-1 softmax+aggregate + relu + layer-2 GEMM + layer-2 logits ----------------
// Warp per dst node. Output: g_xl2h (fp16), g_as2, g_ad2. g_h1 eliminated.
// Dynamic smem: W2 [128][64] staged per block + per-warp staging.
__global__ void fused1_mega_kernel(const float* __restrict__ b1,
                                   const float* __restrict__ W2,
                                   const float* __restrict__ as2v,
                                   const float* __restrict__ ad2v) {
    extern __shared__ float smd[];
    float* sW2   = smd;                              // 8192 floats (32 KB)
    int*   s_src = (int*)(smd + 8192);               // 8*128 ints  (4 KB)
    float* s_e   = smd + 8192 + 1024;                // 8*256 floats (8 KB)
    float* s_h   = smd + 8192 + 1024 + 2048;         // 8*128 floats (4 KB)

    // stage W2 once per block
    {
        const float4* Wv  = (const float4*)W2;
        float4*       sWv = (float4*)sW2;
        for (int i = threadIdx.x; i < 128 * 64 / 4; i += 256) sWv[i] = Wv[i];
    }
    __syncthreads();

    int node  = (blockIdx.x * blockDim.x + threadIdx.x) >> 5;
    int lane  = threadIdx.x & 31;
    int wslot = threadIdx.x >> 5;
    if (node >= N_NODES) return;          // whole-warp exit; no __syncthreads below

    int*   w_src = s_src + wslot * STAGE;
    float* w_e   = s_e   + wslot * STAGE * 2;
    float* w_h   = s_h   + wslot * 128;

    int start = g_ptr[node], end = g_ptr[node + 1];
    int deg = end - start;
    bool sm = (deg <= STAGE);

    float ad0 = g_ad1[node * 2 + 0];
    float ad1 = g_ad1[node * 2 + 1];

    // phase 1: exp + denominator (softmax shift dropped; logits O(1), shift-invariant)
    float den0 = 0.0f, den1 = 0.0f;
    for (int j = start + lane; j < end; j += 32) {
        int s = g_src_csr[j];
        float2 as = ((const float2*)g_as1)[s];
        float e0 = expf(lrelu(as.x + ad0));
        float e1 = expf(lrelu(as.y + ad1));
        if (sm) {
            int k = j - start;
            w_src[k] = s;
            w_e[k * 2 + 0] = e0;
            w_e[k * 2 + 1] = e1;
        } else {
            ((float2*)g_e_csr)[j] = make_float2(e0, e1);
        }
        den0 += e0; den1 += e1;
    }
#pragma unroll
    for (int off = 16; off; off >>= 1) {
        den0 += __shfl_xor_sync(0xffffffff, den0, off);
        den1 += __shfl_xor_sync(0xffffffff, den1, off);
    }
    int h = lane >> 4;
    float rden = 1.0f / (h ? den1 : den0);
    __syncwarp();

    // phase 2: gather + weighted accumulate (lane owns cols 4*lane..4*lane+3)
    float4 bv = ((const float4*)b1)[lane];
    float a0 = bv.x, a1 = bv.y, a2 = bv.z, a3 = bv.w;
    if (sm) {
#pragma unroll 4
        for (int k = 0; k < deg; k++) {
            int s = w_src[k];
            float alpha = w_e[k * 2 + h] * rden;
            uint2 pk = *(const uint2*)(g_xl1h + (size_t)s * 64 + lane * 2);
            float2 f0 = __half22float2(*(__half2*)&pk.x);
            float2 f1 = __half22float2(*(__half2*)&pk.y);
            a0 += alpha * f0.x; a1 += alpha * f0.y;
            a2 += alpha * f1.x; a3 += alpha * f1.y;
        }
    } else {
        for (int j = start; j < end; j++) {
            int s = g_src_csr[j];
            float alpha = g_e_csr[j * 2 + h] * rden;
            uint2 pk = *(const uint2*)(g_xl1h + (size_t)s * 64 + lane * 2);
            float2 f0 = __half22float2(*(__half2*)&pk.x);
            float2 f1 = __half22float2(*(__half2*)&pk.y);
            a0 += alpha * f0.x; a1 += alpha * f0.y;
            a2 += alpha * f1.x; a3 += alpha * f1.y;
        }
    }
    // h1 = relu(agg + b1); stash row in per-warp smem
    float4 hv = make_float4(fmaxf(a0, 0.f), fmaxf(a1, 0.f), fmaxf(a2, 0.f), fmaxf(a3, 0.f));
    *(float4*)(w_h + lane * 4) = hv;
    __syncwarp();

    // layer-2 matvec: lane computes output cols 2*lane, 2*lane+1
    float o0 = 0.0f, o1 = 0.0f;
#pragma unroll 8
    for (int k4 = 0; k4 < 32; k4++) {
        float4 h4 = *(const float4*)(w_h + k4 * 4);         // broadcast
        const float* w = sW2 + (k4 * 4) * 64 + lane * 2;
        float2 w0 = *(const float2*)(w);
        float2 w1 = *(const float2*)(w + 64);
        float2 w2 = *(const float2*)(w + 128);
        float2 w3 = *(const float2*)(w + 192);
        o0 += h4.x * w0.x + h4.y * w1.x + h4.z * w2.x + h4.w * w3.x;
        o1 += h4.x * w0.y + h4.y * w1.y + h4.z * w2.y + h4.w * w3.y;
    }

    // layer-2 attention logits
    float2 a_s = ((const float2*)as2v)[lane];
    float2 a_d = ((const float2*)ad2v)[lane];
    float ps = o0 * a_s.x + o1 * a_s.y;
    float pd = o0 * a_d.x + o1 * a_d.y;
#pragma unroll
    for (int off = 16; off; off >>= 1) {
        ps += __shfl_xor_sync(0xffffffff, ps, off);
        pd += __shfl_xor_sync(0xffffffff, pd, off);
    }
    if (lane == 0) { g_as2[node] = ps; g_ad2[node] = pd; }

    g_xl2h[(size_t)node * 32 + lane] = __floats2half2_rn(o0, o1);
}

// ---------------- fused2: layer-2 softmax + aggregation + bias + relu ----------------
__global__ void fused2_kernel(const float* __restrict__ b2, float* __restrict__ out) {
    __shared__ int   s_src[8][STAGE];
    __shared__ float s_e  [8][STAGE];
    int node = (blockIdx.x * blockDim.x + threadIdx.x) >> 5;
    int lane = threadIdx.x & 31;
    int wslot = (threadIdx.x >> 5);
    if (node >= N_NODES) return;
    int start = g_ptr[node], end = g_ptr[node + 1];
    int deg = end - start;
    bool sm = (deg <= STAGE);

    float adv = g_ad2[node];

    float den = 0.0f;
    for (int j = start + lane; j < end; j += 32) {
        int s = g_src_csr[j];
        float ev = expf(lrelu(g_as2[s] + adv));
        if (sm) {
            int k = j - start;
            s_src[wslot][k] = s;
            s_e[wslot][k] = ev;
        } else {
            g_e_csr[j] = ev;
        }
        den += ev;
    }
#pragma unroll
    for (int off = 16; off; off >>= 1)
        den += __shfl_xor_sync(0xffffffff, den, off);
    float rden = 1.0f / den;
    __syncwarp();

    float2 bv = ((const float2*)b2)[lane];
    float a0 = bv.x, a1 = bv.y;
    if (sm) {
#pragma unroll 4
        for (int k = 0; k < deg; k++) {
            int s = s_src[wslot][k];
            float alpha = s_e[wslot][k] * rden;
            float2 f = __half22float2(g_xl2h[(size_t)s * 32 + lane]);
            a0 += alpha * f.x; a1 += alpha * f.y;
        }
    } else {
        for (int j = start; j < end; j++) {
            int s = g_src_csr[j];
            float alpha = g_e_csr[j] * rden;
            float2 f = __half22float2(g_xl2h[(size_t)s * 32 + lane]);
            a0 += alpha * f.x; a1 += alpha * f.y;
        }
    }
    float2 r = make_float2(fmaxf(a0, 0.f), fmaxf(a1, 0.f));
    ((float2*)(out + (size_t)node * 64))[lane] = r;
}

// ---------------- launch ----------------
extern "C" void kernel_launch(void* const* d_in, const int* in_sizes, int n_in,
                              void* d_out, int out_size) {
    const float *x = 0, *W1 = 0, *W2 = 0;
    const void  *ei = 0;
    const float *v128[3] = {0, 0, 0};
    const float *v64 [3] = {0, 0, 0};
    int n128 = 0, n64 = 0;
    for (int i = 0; i < n_in; i++) {
        int sz = in_sizes[i];
        if      (sz == N_NODES * 128) x  = (const float*)d_in[i];
        else if (sz == 2 * N_EDGES)   ei = d_in[i];
        else if (sz == 128 * 128)     W1 = (const float*)d_in[i];
        else if (sz == 128 * 64)      W2 = (const float*)d_in[i];
        else if (sz == 128 && n128 < 3) v128[n128++] = (const float*)d_in[i];
        else if (sz == 64  && n64  < 3) v64 [n64++]  = (const float*)d_in[i];
    }
    const float* att_src1 = v128[0];
    const float* att_dst1 = v128[1];
    const float* b1       = v128[2];
    const float* att_src2 = v64[0];
    const float* att_dst2 = v64[1];
    const float* b2       = v64[2];
    float* out = (float*)d_out;

    const int TPB = 256;
    const int edge_blocks = (E_TOT + TPB - 1) / TPB;
    const int warp_blocks = (N_NODES * 32 + TPB - 1) / TPB;
    const int gemm_blocks = (N_NODES + 63) / 64;
    const int prep_blocks = (N_NODES + TPB - 1) / TPB;

    const int smem_g1   = (64 * XPITCH + 128 * 128) * 4;    // 99,328 B
    const int smem_mega = (8192 + 1024 + 2048 + 1024) * 4;  // 49,152 B
    cudaFuncSetAttribute(gemm1_kernel,
                         cudaFuncAttributeMaxDynamicSharedMemorySize, smem_g1);
    cudaFuncSetAttribute(fused1_mega_kernel,
                         cudaFuncAttributeMaxDynamicSharedMemorySize, smem_mega);

    // fork/join: CSR chain on the capture (default) stream, gemm1 on s1.
    cudaStream_t s1;
    cudaStreamCreateWithFlags(&s1, cudaStreamNonBlocking);
    cudaEvent_t ev_fork, ev_gemm1;
    cudaEventCreateWithFlags(&ev_fork,  cudaEventDisableTiming);
    cudaEventCreateWithFlags(&ev_gemm1, cudaEventDisableTiming);

    cudaEventRecord(ev_fork, 0);
    cudaStreamWaitEvent(s1, ev_fork, 0);

    // branch A (capture stream): CSR by destination
    prep_kernel<<<prep_blocks, TPB>>>((const long long*)ei);
    hist_kernel<<<edge_blocks, TPB>>>(ei);
    scan_partial_kernel<<<NBLOCKS_SCAN, SBLK>>>();
    scan_final_kernel<<<NBLOCKS_SCAN, SBLK>>>();
    scatter_kernel<<<edge_blocks, TPB>>>(ei);

    // branch B (s1): layer-1 GEMM + fused layer-1 attention logits
    gemm1_kernel<<<gemm_blocks, TPB, smem_g1, s1>>>(x, W1, att_src1, att_dst1);
    cudaEventRecord(ev_gemm1, s1);
    cudaStreamWaitEvent(0, ev_gemm1, 0);

    // join: mega kernel (layer-1 agg + relu + layer-2 GEMM + logits), then layer-2 agg
    fused1_mega_kernel<<<warp_blocks, TPB, smem_mega>>>(b1, W2, att_src2, att_dst2);
    fused2_kernel<<<warp_blocks, TPB>>>(b2, out);

    cudaEventDestroy(ev_fork);
    cudaEventDestroy(ev_gemm1);
    cudaStreamDestroy(s1);
}

// round 12
// speedup vs baseline: 1.2638x; 1.2638x over previous
#include <cuda_runtime.h>
#include <cuda_fp16.h>
#include <math.h>
#include <stdint.h>

#define N_NODES 50000
#define N_EDGES 1600000
#define E_TOT   1650000   // + self loops
#define NEG_SLOPE 0.2f

#define SBLK 256
#define NBLOCKS_SCAN ((N_NODES + SBLK - 1) / SBLK)   // 196
#define STAGE 128        // per-warp smem staging capacity (deg is Poisson(33))
#define XPITCH 132       // padded smem row pitch (16B-aligned, bank-shifted)

// ---------------- scratch (device globals; only referenced from device code) ----------------
__device__ __align__(16) __half2 g_xl1h[N_NODES * 64];  // layer1 feats, fp16 [N,128]
__device__ __align__(16) __half2 g_xl2h[N_NODES * 32];  // layer2 feats, fp16 [N,64]
__device__ __align__(16) float   g_h1 [N_NODES * 128];  // relu(layer1 out), fp32
__device__ __align__(16) float   g_as1[N_NODES * 2];
__device__ __align__(16) float   g_ad1[N_NODES * 2];
__device__ __align__(16) float   g_as2[N_NODES];
__device__ __align__(16) float   g_ad2[N_NODES];

__device__ __align__(16) int   g_deg [N_NODES];
__device__ __align__(16) int   g_ptr [N_NODES + 1];
__device__ __align__(16) int   g_work[N_NODES];
__device__ __align__(16) int   g_src_csr[E_TOT];
__device__ __align__(16) float g_e_csr[E_TOT * 2];   // fallback only (deg > STAGE)
__device__ __align__(16) int   g_bsum[NBLOCKS_SCAN];

__device__ int g_e64;

// ---------------- helpers ----------------
__device__ __forceinline__ float lrelu(float x) {
    return x >= 0.0f ? x : NEG_SLOPE * x;
}

__device__ __forceinline__ void edge_sd(const void* ei, int is64, int e, int& s, int& d) {
    if (e >= N_EDGES) { s = d = e - N_EDGES; return; }
    if (is64) {
        const long long* p = (const long long*)ei;
        s = (int)p[e];
        d = (int)p[N_EDGES + e];
    } else {
        const int* p = (const int*)ei;
        s = p[e];
        d = p[N_EDGES + e];
    }
}

__device__ __forceinline__ int warp_incl_scan(int v, int lane) {
#pragma unroll
    for (int off = 1; off < 32; off <<= 1) {
        int n = __shfl_up_sync(0xffffffff, v, off);
        if (lane >= off) v += n;
    }
    return v;
}

// ---------------- graph preprocessing ----------------
__global__ void prep_kernel(const long long* ei) {
    int i = blockIdx.x * blockDim.x + threadIdx.x;
    if (i < N_NODES) g_deg[i] = 0;
    if (blockIdx.x == 0) {
        __shared__ int bad;
        if (threadIdx.x == 0) bad = 0;
        __syncthreads();
        long long v = ei[threadIdx.x];
        if (v < 0 || v >= N_NODES) bad = 1;
        __syncthreads();
        if (threadIdx.x == 0) g_e64 = bad ? 0 : 1;
    }
}

__global__ void hist_kernel(const void* __restrict__ ei) {
    int e = blockIdx.x * blockDim.x + threadIdx.x;
    if (e >= E_TOT) return;
    int s, d; edge_sd(ei, g_e64, e, s, d);
    atomicAdd(&g_deg[d], 1);
}

__global__ void scan_partial_kernel() {
    int i = blockIdx.x * SBLK + threadIdx.x;
    int v = (i < N_NODES) ? g_deg[i] : 0;
    __shared__ int ws[8];
    int lane = threadIdx.x & 31, wid = threadIdx.x >> 5;
    int s = v;
#pragma unroll
    for (int off = 16; off; off >>= 1) s += __shfl_xor_sync(0xffffffff, s, off);
    if (lane == 0) ws[wid] = s;
    __syncthreads();
    if (threadIdx.x == 0) {
        int t = 0;
#pragma unroll
        for (int w = 0; w < 8; w++) t += ws[w];
        g_bsum[blockIdx.x] = t;
    }
}

__global__ void scan_final_kernel() {
    __shared__ int s_boff[NBLOCKS_SCAN];
    __shared__ int ws2[8];
    __shared__ int ws[8];
    int t = threadIdx.x;
    int lane = t & 31, wid = t >> 5;

    {
        int v = (t < NBLOCKS_SCAN) ? g_bsum[t] : 0;
        int inc = warp_incl_scan(v, lane);
        if (lane == 31) ws2[wid] = inc;
        __syncthreads();
        if (wid == 0) {
            int wv = (lane < 8) ? ws2[lane] : 0;
            int winc = warp_incl_scan(wv, lane);
            if (lane < 8) ws2[lane] = winc;
        }
        __syncthreads();
        int excl = inc - v + (wid ? ws2[wid - 1] : 0);
        if (t < NBLOCKS_SCAN) s_boff[t] = excl;
        if (blockIdx.x == 0 && t == NBLOCKS_SCAN - 1) g_ptr[N_NODES] = excl + v;
    }
    __syncthreads();

    int i = blockIdx.x * SBLK + t;
    int v = (i < N_NODES) ? g_deg[i] : 0;
    int inc = warp_incl_scan(v, lane);
    if (lane == 31) ws[wid] = inc;
    __syncthreads();
    if (wid == 0) {
        int wv = (lane < 8) ? ws[lane] : 0;
        int winc = warp_incl_scan(wv, lane);
        if (lane < 8) ws[lane] = winc;
    }
    __syncthreads();
    int excl = inc - v + (wid ? ws[wid - 1] : 0) + s_boff[blockIdx.x];
    if (i < N_NODES) { g_ptr[i] = excl; g_work[i] = excl; }
}

__global__ void scatter_kernel(const void* __restrict__ ei) {
    int e = blockIdx.x * blockDim.x + threadIdx.x;
    if (e >= E_TOT) return;
    int s, d; edge_sd(ei, g_e64, e, s, d);
    int pos = atomicAdd(&g_work[d], 1);
    g_src_csr[pos] = s;
}

// ---------------- register-tiled GEMM (k4-chunked), fp16 output + fused attention logits ----------------
// Tile: 64 rows x NCOL cols per 256-thread block. Thread computes RPT rows x 4 cols.
// MODE 1: X = x    -> g_xl1h (NCOL=128, TCN=32, RPT=8); logits -> g_as1/g_ad1 (H=2).
// MODE 2: X = g_h1 -> g_xl2h (NCOL=64,  TCN=16, RPT=4); logits -> g_as2/g_ad2 (H=1).
template<int NCOL, int MODE, int TCN, int RPT>
__global__ void gemm_kernel(const float* __restrict__ Xext,
                            const float* __restrict__ W,
                            const float* __restrict__ att_src,
                            const float* __restrict__ att_dst) {
    extern __shared__ float sm[];
    float* sX = sm;                       // [64][XPITCH]
    float* sW = sm + 64 * XPITCH;         // [128][NCOL]

    const float* X = (MODE == 1) ? Xext : g_h1;
    __half2*     out = (MODE == 1) ? g_xl1h : g_xl2h;
    constexpr int OUTP = NCOL / 2;        // half2 row pitch

    const int tid  = threadIdx.x;
    const int row0 = blockIdx.x * 64;
    const int tc   = tid % TCN;
    const int tr   = tid / TCN;

    {
        const float4* Wv  = (const float4*)W;
        float4*       sWv = (float4*)sW;
        const int nv = 128 * NCOL / 4;
        for (int i = tid; i < nv; i += 256) sWv[i] = Wv[i];
    }
    for (int i = tid; i < 64 * 32; i += 256) {
        int r = i >> 5, c4 = i & 31;
        int row = row0 + r;
        float4 v = (row < N_NODES) ? ((const float4*)(X + (size_t)row * 128))[c4]
                                   : make_float4(0.f, 0.f, 0.f, 0.f);
        *(float4*)(sX + r * XPITCH + c4 * 4) = v;
    }
    __syncthreads();

    float acc[RPT][4];
#pragma unroll
    for (int i = 0; i < RPT; i++)
#pragma unroll
        for (int c = 0; c < 4; c++) acc[i][c] = 0.0f;

    const float* xbase = sX + tr * RPT * XPITCH;
#pragma unroll 4
    for (int k4 = 0; k4 < 32; k4++) {
        float4 w0 = *(const float4*)(sW + (k4 * 4 + 0) * NCOL + tc * 4);
        float4 w1 = *(const float4*)(sW + (k4 * 4 + 1) * NCOL + tc * 4);
        float4 w2 = *(const float4*)(sW + (k4 * 4 + 2) * NCOL + tc * 4);
        float4 w3 = *(const float4*)(sW + (k4 * 4 + 3) * NCOL + tc * 4);
#pragma unroll
        for (int i = 0; i < RPT; i++) {
            float4 a = *(const float4*)(xbase + i * XPITCH + k4 * 4);
            acc[i][0] += a.x * w0.x + a.y * w1.x + a.z * w2.x + a.w * w3.x;
            acc[i][1] += a.x * w0.y + a.y * w1.y + a.z * w2.y + a.w * w3.y;
            acc[i][2] += a.x * w0.z + a.y * w1.z + a.z * w2.z + a.w * w3.z;
            acc[i][3] += a.x * w0.w + a.y * w1.w + a.z * w2.w + a.w * w3.w;
        }
    }

    float4 as4 = ((const float4*)att_src)[tc];
    float4 ad4 = ((const float4*)att_dst)[tc];
#pragma unroll
    for (int i = 0; i < RPT; i++) {
        int row = row0 + tr * RPT + i;
        float ps = acc[i][0] * as4.x + acc[i][1] * as4.y + acc[i][2] * as4.z + acc[i][3] * as4.w;
        float pd = acc[i][0] * ad4.x + acc[i][1] * ad4.y + acc[i][2] * ad4.z + acc[i][3] * ad4.w;
#pragma unroll
        for (int off = 8; off; off >>= 1) {
            ps += __shfl_xor_sync(0xffffffffu, ps, off);
            pd += __shfl_xor_sync(0xffffffffu, pd, off);
        }
        if ((tid & 15) == 0 && row < N_NODES) {
            if (MODE == 1) {
                int h = (tid >> 4) & 1;
                g_as1[row * 2 + h] = ps;
                g_ad1[row * 2 + h] = pd;
            } else {
                g_as2[row] = ps;
                g_ad2[row] = pd;
            }
        }
        if (row < N_NODES) {
            __half2 h0 = __floats2half2_rn(acc[i][0], acc[i][1]);
            __half2 h1 = __floats2half2_rn(acc[i][2], acc[i][3]);
            uint2 pk = make_uint2(*(unsigned*)&h0, *(unsigned*)&h1);
            *(uint2*)(out + (size_t)row * OUTP + tc * 2) = pk;   // 8B store
        }
    }
}

// ---------------- fused softmax + aggregation (CSR, warp per dst node, fp16 gather) ----------------
__global__ void fused1_kernel(const float* __restrict__ b1) {
    __shared__ int   s_src[8][STAGE];
    __shared__ float s_e  [8][STAGE * 2];
    int node = (blockIdx.x * blockDim.x + threadIdx.x) >> 5;
    int lane = threadIdx.x & 31;
    int wslot = (threadIdx.x >> 5);
    if (node >= N_NODES) return;
    int start = g_ptr[node], end = g_ptr[node + 1];
    int deg = end - start;
    bool sm = (deg <= STAGE);

    float ad0 = g_ad1[node * 2 + 0];
    float ad1 = g_ad1[node * 2 + 1];

    float den0 = 0.0f, den1 = 0.0f;
    for (int j = start + lane; j < end; j += 32) {
        int s = g_src_csr[j];
        float2 as = ((const float2*)g_as1)[s];
        float e0 = expf(lrelu(as.x + ad0));
        float e1 = expf(lrelu(as.y + ad1));
        if (sm) {
            int k = j - start;
            s_src[wslot][k] = s;
            s_e[wslot][k * 2 + 0] = e0;
            s_e[wslot][k * 2 + 1] = e1;
        } else {
            ((float2*)g_e_csr)[j] = make_float2(e0, e1);
        }
        den0 += e0; den1 += e1;
    }
#pragma unroll
    for (int off = 16; off; off >>= 1) {
        den0 += __shfl_xor_sync(0xffffffff, den0, off);
        den1 += __shfl_xor_sync(0xffffffff, den1, off);
    }
    int h = lane >> 4;
    float rden = 1.0f / (h ? den1 : den0);
    __syncwarp();

    float4 bv = ((const float4*)b1)[lane];
    float a0 = bv.x, a1 = bv.y, a2 = bv.z, a3 = bv.w;
    if (sm) {
#pragma unroll 4
        for (int k = 0; k < deg; k++) {
            int s = s_src[wslot][k];
            float alpha = s_e[wslot][k * 2 + h] * rden;
            uint2 pk = *(const uint2*)(g_xl1h + (size_t)s * 64 + lane * 2);
            float2 f0 = __half22float2(*(__half2*)&pk.x);
            float2 f1 = __half22float2(*(__half2*)&pk.y);
            a0 += alpha * f0.x; a1 += alpha * f0.y;
            a2 += alpha * f1.x; a3 += alpha * f1.y;
        }
    } else {
        for (int j = start; j < end; j++) {
            int s = g_src_csr[j];
            float alpha = g_e_csr[j * 2 + h] * rden;
            uint2 pk = *(const uint2*)(g_xl1h + (size_t)s * 64 + lane * 2);
            float2 f0 = __half22float2(*(__half2*)&pk.x);
            float2 f1 = __half22float2(*(__half2*)&pk.y);
            a0 += alpha * f0.x; a1 += alpha * f0.y;
            a2 += alpha * f1.x; a3 += alpha * f1.y;
        }
    }
    float4 r = make_float4(fmaxf(a0, 0.f), fmaxf(a1, 0.f), fmaxf(a2, 0.f), fmaxf(a3, 0.f));
    ((float4*)(g_h1 + (size_t)node * 128))[lane] = r;
}

__global__ void fused2_kernel(const float* __restrict__ b2, float* __restrict__ out) {
    __shared__ int   s_src[8][STAGE];
    __shared__ float s_e  [8][STAGE];
    int node = (blockIdx.x * blockDim.x + threadIdx.x) >> 5;
    int lane = threadIdx.x & 31;
    int wslot = (threadIdx.x >> 5);
    if (node >= N_NODES) return;
    int start = g_ptr[node], end = g_ptr[node + 1];
    int deg = end - start;
    bool sm = (deg <= STAGE);

    float adv = g_ad2[node];

    float den = 0.0f;
    for (int j = start + lane; j < end; j += 32) {
        int s = g_src_csr[j];
        float ev = expf(lrelu(g_as2[s] + adv));
        if (sm) {
            int k = j - start;
            s_src[wslot][k] = s;
            s_e[wslot][k] = ev;
        } else {
            g_e_csr[j] = ev;
        }
        den += ev;
    }
#pragma unroll
    for (int off = 16; off; off >>= 1)
        den += __shfl_xor_sync(0xffffffff, den, off);
    float rden = 1.0f / den;
    __syncwarp();

    float2 bv = ((const float2*)b2)[lane];
    float a0 = bv.x, a1 = bv.y;
    if (sm) {
#pragma unroll 4
        for (int k = 0; k < deg; k++) {
            int s = s_src[wslot][k];
            float alpha = s_e[wslot][k] * rden;
            float2 f = __half22float2(g_xl2h[(size_t)s * 32 + lane]);
            a0 += alpha * f.x; a1 += alpha * f.y;
        }
    } else {
        for (int j = start; j < end; j++) {
            int s = g_src_csr[j];
            float alpha = g_e_csr[j] * rden;
            float2 f = __half22float2(g_xl2h[(size_t)s * 32 + lane]);
            a0 += alpha * f.x; a1 += alpha * f.y;
        }
    }
    float2 r = make_float2(fmaxf(a0, 0.f), fmaxf(a1, 0.f));
    ((float2*)(out + (size_t)node * 64))[lane] = r;
}

// ---------------- launch ----------------
extern "C" void kernel_launch(void* const* d_in, const int* in_sizes, int n_in,
                              void* d_out, int out_size) {
    const float *x = 0, *W1 = 0, *W2 = 0;
    const void  *ei = 0;
    const float *v128[3] = {0, 0, 0};
    const float *v64 [3] = {0, 0, 0};
    int n128 = 0, n64 = 0;
    for (int i = 0; i < n_in; i++) {
        int sz = in_sizes[i];
        if      (sz == N_NODES * 128) x  = (const float*)d_in[i];
        else if (sz == 2 * N_EDGES)   ei = d_in[i];
        else if (sz == 128 * 128)     W1 = (const float*)d_in[i];
        else if (sz == 128 * 64)      W2 = (const float*)d_in[i];
        else if (sz == 128 && n128 < 3) v128[n128++] = (const float*)d_in[i];
        else if (sz == 64  && n64  < 3) v64 [n64++]  = (const float*)d_in[i];
    }
    const float* att_src1 = v128[0];
    const float* att_dst1 = v128[1];
    const float* b1       = v128[2];
    const float* att_src2 = v64[0];
    const float* att_dst2 = v64[1];
    const float* b2       = v64[2];
    float* out = (float*)d_out;

    const int TPB = 256;
    const int edge_blocks = (E_TOT + TPB - 1) / TPB;
    const int warp_blocks = (N_NODES * 32 + TPB - 1) / TPB;
    const int gemm_blocks = (N_NODES + 63) / 64;
    const int prep_blocks = (N_NODES + TPB - 1) / TPB;

    const int smem1 = (64 * XPITCH + 128 * 128) * 4;           // 99,328 B
    const int smem2 = (64 * XPITCH + 128 * 64) * 4;            // 66,560 B
    cudaFuncSetAttribute(gemm_kernel<128, 1, 32, 8>,
                         cudaFuncAttributeMaxDynamicSharedMemorySize, smem1);
    cudaFuncSetAttribute(gemm_kernel<64, 2, 16, 4>,
                         cudaFuncAttributeMaxDynamicSharedMemorySize, smem2);

    // fork/join: CSR chain on the capture (default) stream, gemm1 on s1.
    cudaStream_t s1;
    cudaStreamCreateWithFlags(&s1, cudaStreamNonBlocking);
    cudaEvent_t ev_fork, ev_gemm1;
    cudaEventCreateWithFlags(&ev_fork,  cudaEventDisableTiming);
    cudaEventCreateWithFlags(&ev_gemm1, cudaEventDisableTiming);

    cudaEventRecord(ev_fork, 0);
    cudaStreamWaitEvent(s1, ev_fork, 0);

    // branch A (capture stream): CSR by destination
    prep_kernel<<<prep_blocks, TPB>>>((const long long*)ei);
    hist_kernel<<<edge_blocks, TPB>>>(ei);
    scan_partial_kernel<<<NBLOCKS_SCAN, SBLK>>>();
    scan_final_kernel<<<NBLOCKS_SCAN, SBLK>>>();
    scatter_kernel<<<edge_blocks, TPB>>>(ei);

    // branch B (s1): layer-1 GEMM + fused layer-1 attention logits
    gemm_kernel<128, 1, 32, 8><<<gemm_blocks, TPB, smem1, s1>>>(x, W1, att_src1, att_dst1);
    cudaEventRecord(ev_gemm1, s1);
    cudaStreamWaitEvent(0, ev_gemm1, 0);

    // join: rest sequential on the capture stream
    fused1_kernel<<<warp_blocks, TPB>>>(b1);
    gemm_kernel<64, 2, 16, 4><<<gemm_blocks, TPB, smem2>>>(x, W2, att_src2, att_dst2);
    fused2_kernel<<<warp_blocks, TPB>>>(b2, out);

    cudaEventDestroy(ev_fork);
    cudaEventDestroy(ev_gemm1);
    cudaStreamDestroy(s1);
}